// round 1
// baseline (speedup 1.0000x reference)
#include <cuda_runtime.h>
#include <cstdint>

#define BATCH 64
#define NW    256
#define HDIM  768

// BM25 constants (match reference; ALPHA*BETA computed in double then truncated)
__device__ __constant__ float c_dummy; // keep nvcc happy about unused warnings
#define K1f    0.1f
#define Bpf    1.2f
#define AVDLf  50.0f
#define ABf    ((float)(0.1 / 768.0))   /* ALPHA*BETA */
#define EMWf   0.9f                     /* 1 - BETA   */

// ---- scratch (no allocations allowed) ----
__device__ float    g_qmask[BATCH * NW];
__device__ float    g_dmask[BATCH * NW];
__device__ unsigned g_qkey [BATCH * NW];
__device__ unsigned g_dkey [BATCH * NW];
// per-(b,q) partial etdf sums, 8 deterministic slots = 2 n-CTAs x 4 n-warps
__device__ float    g_part [BATCH * NW * 8];

// ============================================================
// Kernel 1: pack ids -> key (ids are in [0,32), 4 x 8 bits) and null mask
// ============================================================
__global__ void prep_kernel(const int* __restrict__ qids, const int* __restrict__ dids) {
    int i = blockIdx.x * blockDim.x + threadIdx.x;
    if (i >= BATCH * NW) return;
    const int* q = qids + i * 4;
    unsigned qk = (unsigned)q[0] | ((unsigned)q[1] << 8) | ((unsigned)q[2] << 16) | ((unsigned)q[3] << 24);
    const int* d = dids + i * 4;
    unsigned dk = (unsigned)d[0] | ((unsigned)d[1] << 8) | ((unsigned)d[2] << 16) | ((unsigned)d[3] << 24);
    g_qkey[i] = qk;
    g_dkey[i] = dk;
    g_qmask[i] = qk ? 1.0f : 0.0f;  // all-zero ids => key 0 => mask 0
    g_dmask[i] = dk ? 1.0f : 0.0f;
}

// ============================================================
// Kernel 2: batched GEMM C[b] = Qm[b] (256x768) * Dm[b]^T, tf32 mma.sync
//   tile: BM=128 BN=128 BK=32, 8 warps = 2(m) x 4(n), warp tile 64x32
//   fused epilogue: write d_expanded_tf + per-row partial etdf reduce
// ============================================================
#define BM 128
#define BN 128
#define BK 32
#define SMSTRIDE 36   // BK + 4 pad: fragment loads conflict-free

__device__ __forceinline__ unsigned f2tf32(float x) {
    unsigned r;
    asm("cvt.rna.tf32.f32 %0, %1;" : "=r"(r) : "f"(x));
    return r;
}

__device__ __forceinline__ void mma_tf32(float& c0, float& c1, float& c2, float& c3,
                                         unsigned a0, unsigned a1, unsigned a2, unsigned a3,
                                         unsigned b0, unsigned b1) {
    asm volatile(
        "mma.sync.aligned.m16n8k8.row.col.f32.tf32.tf32.f32 "
        "{%0,%1,%2,%3}, {%4,%5,%6,%7}, {%8,%9}, {%0,%1,%2,%3};"
        : "+f"(c0), "+f"(c1), "+f"(c2), "+f"(c3)
        : "r"(a0), "r"(a1), "r"(a2), "r"(a3), "r"(b0), "r"(b1));
}

__global__ __launch_bounds__(256, 2)
void gemm_kernel(const float* __restrict__ qrep, const float* __restrict__ drep,
                 const int* __restrict__ dtfs, float* __restrict__ otf) {
    __shared__ unsigned As[BM * SMSTRIDE];
    __shared__ unsigned Bs[BN * SMSTRIDE];

    const int b   = blockIdx.z;
    const int bm0 = blockIdx.y * BM;
    const int bn0 = blockIdx.x * BN;
    const int tid = threadIdx.x;
    const int lane = tid & 31;
    const int warpId = tid >> 5;
    const int warpM = warpId >> 2;      // 0..1
    const int warpN = warpId & 3;       // 0..3
    const int wm0 = warpM * 64;
    const int wn0 = warpN * 32;

    const float* Ag = qrep + ((size_t)b * NW + bm0) * HDIM;
    const float* Bg = drep + ((size_t)b * NW + bn0) * HDIM;
    const float* qm = g_qmask + b * NW + bm0;
    const float* dm = g_dmask + b * NW + bn0;

    float acc[4][4][4];
#pragma unroll
    for (int i = 0; i < 4; i++)
#pragma unroll
        for (int j = 0; j < 4; j++)
#pragma unroll
            for (int k = 0; k < 4; k++) acc[i][j][k] = 0.0f;

    for (int k0 = 0; k0 < HDIM; k0 += BK) {
        // load A tile (masked, tf32-rounded)
#pragma unroll
        for (int v = tid; v < BM * (BK / 4); v += 256) {
            int row = v >> 3, kv = v & 7;
            float4 x = *(const float4*)(Ag + row * HDIM + k0 + kv * 4);
            float m = qm[row];
            unsigned* dst = &As[row * SMSTRIDE + kv * 4];
            dst[0] = f2tf32(x.x * m); dst[1] = f2tf32(x.y * m);
            dst[2] = f2tf32(x.z * m); dst[3] = f2tf32(x.w * m);
        }
        // load B tile (masked, tf32-rounded)
#pragma unroll
        for (int v = tid; v < BN * (BK / 4); v += 256) {
            int row = v >> 3, kv = v & 7;
            float4 x = *(const float4*)(Bg + row * HDIM + k0 + kv * 4);
            float m = dm[row];
            unsigned* dst = &Bs[row * SMSTRIDE + kv * 4];
            dst[0] = f2tf32(x.x * m); dst[1] = f2tf32(x.y * m);
            dst[2] = f2tf32(x.z * m); dst[3] = f2tf32(x.w * m);
        }
        __syncthreads();

#pragma unroll
        for (int kk = 0; kk < BK; kk += 8) {
            unsigned bf0[4], bf1[4];
#pragma unroll
            for (int ni = 0; ni < 4; ni++) {
                int col = wn0 + ni * 8 + (lane >> 2);
                bf0[ni] = Bs[col * SMSTRIDE + kk + (lane & 3)];
                bf1[ni] = Bs[col * SMSTRIDE + kk + 4 + (lane & 3)];
            }
#pragma unroll
            for (int mi = 0; mi < 4; mi++) {
                int row = wm0 + mi * 16 + (lane >> 2);
                unsigned a0 = As[row * SMSTRIDE + kk + (lane & 3)];
                unsigned a1 = As[(row + 8) * SMSTRIDE + kk + (lane & 3)];
                unsigned a2 = As[row * SMSTRIDE + kk + 4 + (lane & 3)];
                unsigned a3 = As[(row + 8) * SMSTRIDE + kk + 4 + (lane & 3)];
#pragma unroll
                for (int ni = 0; ni < 4; ni++) {
                    mma_tf32(acc[mi][ni][0], acc[mi][ni][1], acc[mi][ni][2], acc[mi][ni][3],
                             a0, a1, a2, a3, bf0[ni], bf1[ni]);
                }
            }
        }
        __syncthreads();
    }

    // ---------------- epilogue ----------------
    const unsigned* qkeyp = g_qkey + b * NW;
    const unsigned* dkeyp = g_dkey + b * NW;
    const int* tfp = dtfs + b * NW;
    float* outb = otf + (size_t)b * NW * NW;

    float rowsum[8];
#pragma unroll
    for (int i = 0; i < 8; i++) rowsum[i] = 0.0f;

#pragma unroll
    for (int mi = 0; mi < 4; mi++) {
        int r0 = bm0 + wm0 + mi * 16 + (lane >> 2);
        int r1 = r0 + 8;
        unsigned qk0 = qkeyp[r0], qk1 = qkeyp[r1];
#pragma unroll
        for (int ni = 0; ni < 4; ni++) {
            int c0col = bn0 + wn0 + ni * 8 + (lane & 3) * 2;
            unsigned dk0 = dkeyp[c0col], dk1 = dkeyp[c0col + 1];
            float tf0 = (float)tfp[c0col], tf1 = (float)tfp[c0col + 1];
            float v00 = acc[mi][ni][0], v01 = acc[mi][ni][1];
            float v10 = acc[mi][ni][2], v11 = acc[mi][ni][3];
            *(float2*)(outb + (size_t)r0 * NW + c0col) = make_float2(v00, v01);
            *(float2*)(outb + (size_t)r1 * NW + c0col) = make_float2(v10, v11);
            rowsum[mi * 2]     += (v00 * ABf + (qk0 == dk0 ? EMWf : 0.0f)) * tf0
                                + (v01 * ABf + (qk0 == dk1 ? EMWf : 0.0f)) * tf1;
            rowsum[mi * 2 + 1] += (v10 * ABf + (qk1 == dk0 ? EMWf : 0.0f)) * tf0
                                + (v11 * ABf + (qk1 == dk1 ? EMWf : 0.0f)) * tf1;
        }
    }

    // reduce across the quad (4 lanes share a row), write deterministic slot
    const int slot = blockIdx.x * 4 + warpN;  // 0..7
#pragma unroll
    for (int i = 0; i < 8; i++) {
        float s = rowsum[i];
        s += __shfl_xor_sync(0xffffffff, s, 1);
        s += __shfl_xor_sync(0xffffffff, s, 2);
        if ((lane & 3) == 0) {
            int r = bm0 + wm0 + (i >> 1) * 16 + (lane >> 2) + (i & 1) * 8;
            g_part[(b * NW + r) * 8 + slot] = s;
        }
    }
}

// ============================================================
// Kernel 3: finish BM25 score per batch
// ============================================================
__global__ void final_kernel(const float* __restrict__ qtw, const int* __restrict__ dtfs,
                             float* __restrict__ out) {
    __shared__ float red[256];
    int b = blockIdx.x;
    int t = threadIdx.x;

    float tf = (float)dtfs[b * NW + t];
    red[t] = tf;
    __syncthreads();
#pragma unroll
    for (int s = 128; s > 0; s >>= 1) {
        if (t < s) red[t] += red[t + s];
        __syncthreads();
    }
    float dl = red[0];
    __syncthreads();

    const float* p = g_part + (b * NW + t) * 8;
    float etdf = ((p[0] + p[1]) + (p[2] + p[3])) + ((p[4] + p[5]) + (p[6] + p[7]));
    float denom = etdf * (1.0f + K1f);
    float nom   = etdf + K1f * (1.0f - Bpf + Bpf * dl / AVDLf);
    float dtw   = denom / (nom + 1e-8f);
    float v = qtw[b * NW + t] * dtw;

    red[t] = v;
    __syncthreads();
#pragma unroll
    for (int s = 128; s > 0; s >>= 1) {
        if (t < s) red[t] += red[t + s];
        __syncthreads();
    }
    if (t == 0) out[b] = red[0];
}

// ============================================================
// Launch: outputs are concat(s[64], d_expanded_tf[64*256*256]) in f32
// ============================================================
extern "C" void kernel_launch(void* const* d_in, const int* in_sizes, int n_in,
                              void* d_out, int out_size) {
    const float* q_rep = (const float*)d_in[0];
    const float* d_rep = (const float*)d_in[1];
    const float* qtw   = (const float*)d_in[2];
    const int*   qids  = (const int*)d_in[3];
    const int*   dids  = (const int*)d_in[4];
    const int*   dtfs  = (const int*)d_in[5];

    float* out = (float*)d_out;
    float* otf = out + BATCH;  // d_expanded_tf region

    prep_kernel<<<(BATCH * NW + 255) / 256, 256>>>(qids, dids);

    dim3 grid(NW / BN, NW / BM, BATCH);  // (2, 2, 64)
    gemm_kernel<<<grid, 256>>>(q_rep, d_rep, dtfs, otf);

    final_kernel<<<BATCH, 256>>>(qtw, dtfs, out);
}

// round 3
// speedup vs baseline: 1.7079x; 1.7079x over previous
#include <cuda_runtime.h>
#include <cstdint>

#define BATCH 64
#define NW    256
#define HDIM  768
#define BM    128
#define BN    256
#define BK    32
#define NIT   (HDIM / BK)   // 24

#define K1f    0.1f
#define Bpf    1.2f
#define AVDLf  50.0f
#define ABf    ((float)(0.1 / 768.0))   /* ALPHA*BETA */
#define EMWf   0.9f                     /* 1 - BETA   */

// per-(b,q) complete etdf (one slot: BN=256 covers all d-cols in one CTA)
__device__ float g_part[BATCH * NW];

__device__ __forceinline__ void mma_tf32(float& c0, float& c1, float& c2, float& c3,
                                         unsigned a0, unsigned a1, unsigned a2, unsigned a3,
                                         unsigned b0, unsigned b1) {
    asm volatile(
        "mma.sync.aligned.m16n8k8.row.col.f32.tf32.tf32.f32 "
        "{%0,%1,%2,%3}, {%4,%5,%6,%7}, {%8,%9}, {%0,%1,%2,%3};"
        : "+f"(c0), "+f"(c1), "+f"(c2), "+f"(c3)
        : "r"(a0), "r"(a1), "r"(a2), "r"(a3), "r"(b0), "r"(b1));
}

__device__ __forceinline__ void cp16(unsigned dst_smem, const void* src) {
    asm volatile("cp.async.cg.shared.global [%0], [%1], 16;" :: "r"(dst_smem), "l"(src));
}
__device__ __forceinline__ void cp_commit() { asm volatile("cp.async.commit_group;"); }

// round fp32 bits at the tf32 truncation point (HW drops low 13 mantissa bits)
__device__ __forceinline__ unsigned rnd(unsigned x) { return x + 0x1000u; }

// ============================================================
// GEMM + fused epilogue. grid (2, 64): (M-block, batch). 256 thr.
// warp grid 2x4, warp tile 64x64. 2-stage cp.async pipeline.
// smem: A[2][128*32] + B[2][256*32] words = 96 KB
// ============================================================
__global__ __launch_bounds__(256, 1)
void gemm_kernel(const float* __restrict__ qrep, const float* __restrict__ drep,
                 const int* __restrict__ qids, const int* __restrict__ dids,
                 const int* __restrict__ dtfs, float* __restrict__ otf) {
    extern __shared__ unsigned sm[];
    const int b   = blockIdx.y;
    const int bm0 = blockIdx.x * BM;
    const int tid = threadIdx.x;
    const int lane = tid & 31;
    const int warpId = tid >> 5;
    const int wm0 = (warpId >> 2) * 64;
    const int wn0 = (warpId & 3) * 64;
    const int q  = lane & 3;
    const int lq = lane >> 2;

    const float* Ag = qrep + ((size_t)b * NW + bm0) * HDIM;
    const float* Bg = drep + (size_t)b * NW * HDIM;

    const unsigned smbase = (unsigned)__cvta_generic_to_shared(sm);
    const unsigned Aoff = 0;
    const unsigned Boff = 2 * BM * BK;  // word offset

    float acc[4][8][4];
#pragma unroll
    for (int i = 0; i < 4; i++)
#pragma unroll
        for (int j = 0; j < 8; j++)
#pragma unroll
            for (int k = 0; k < 4; k++) acc[i][j][k] = 0.0f;

    // ---- async tile loaders (16B chunks, XOR-swizzled 128B rows) ----
    auto loadA = [&](int it, int s) {
        const float* src = Ag + it * BK;
        unsigned dstb = smbase + (Aoff + s * BM * BK) * 4;
#pragma unroll
        for (int i = 0; i < 4; i++) {
            int c = tid + i * 256;
            int r = c >> 3, g = c & 7;
            unsigned w = r * 32 + ((g ^ (r & 7)) << 2);
            cp16(dstb + w * 4, src + (size_t)r * HDIM + g * 4);
        }
    };
    auto loadB = [&](int it, int s) {
        const float* src = Bg + it * BK;
        unsigned dstb = smbase + (Boff + s * BN * BK) * 4;
#pragma unroll
        for (int i = 0; i < 8; i++) {
            int c = tid + i * 256;
            int r = c >> 3, g = c & 7;
            unsigned w = r * 32 + ((g ^ (r & 7)) << 2);
            cp16(dstb + w * 4, src + (size_t)r * HDIM + g * 4);
        }
    };

    loadA(0, 0); loadB(0, 0); cp_commit();

    for (int it = 0; it < NIT; ++it) {
        if (it + 1 < NIT) {
            int s = (it + 1) & 1;
            loadA(it + 1, s); loadB(it + 1, s); cp_commit();
            asm volatile("cp.async.wait_group 1;");
        } else {
            asm volatile("cp.async.wait_group 0;");
        }
        __syncthreads();

        const unsigned* Ast = sm + Aoff + (it & 1) * BM * BK;
        const unsigned* Bst = sm + Boff + (it & 1) * BN * BK;

#pragma unroll
        for (int kk4 = 0; kk4 < 4; kk4++) {       // K-step of 8
            const int g0 = kk4 * 2, g1 = kk4 * 2 + 1;
            unsigned bf0[8], bf1[8];
#pragma unroll
            for (int ni = 0; ni < 8; ni++) {
                int cB = wn0 + ni * 8 + lq;
                bf0[ni] = rnd(Bst[cB * 32 + ((g0 ^ (cB & 7)) << 2) + q]);
                bf1[ni] = rnd(Bst[cB * 32 + ((g1 ^ (cB & 7)) << 2) + q]);
            }
#pragma unroll
            for (int mi = 0; mi < 4; mi++) {
                int r0 = wm0 + mi * 16 + lq, r1 = r0 + 8;
                unsigned a0 = rnd(Ast[r0 * 32 + ((g0 ^ (r0 & 7)) << 2) + q]);
                unsigned a1 = rnd(Ast[r1 * 32 + ((g0 ^ (r1 & 7)) << 2) + q]);
                unsigned a2 = rnd(Ast[r0 * 32 + ((g1 ^ (r0 & 7)) << 2) + q]);
                unsigned a3 = rnd(Ast[r1 * 32 + ((g1 ^ (r1 & 7)) << 2) + q]);
#pragma unroll
                for (int ni = 0; ni < 8; ni++)
                    mma_tf32(acc[mi][ni][0], acc[mi][ni][1], acc[mi][ni][2], acc[mi][ni][3],
                             a0, a1, a2, a3, bf0[ni], bf1[ni]);
            }
        }
        __syncthreads();
    }

    // ---------------- epilogue ----------------
    // overlay smem: keys, tf, reduction buffers
    unsigned* qk_s  = sm;                    // 128
    unsigned* dk_s  = sm + 128;              // 256
    float*    dtf_s = (float*)(sm + 384);    // 256
    float*    red_s = (float*)(sm + 640);    // 4 * 128

    if (tid < BM) {
        int4 v = ((const int4*)qids)[b * NW + bm0 + tid];
        qk_s[tid] = (unsigned)v.x | ((unsigned)v.y << 8) | ((unsigned)v.z << 16) | ((unsigned)v.w << 24);
    }
    {
        int4 v = ((const int4*)dids)[b * NW + tid];
        dk_s[tid] = (unsigned)v.x | ((unsigned)v.y << 8) | ((unsigned)v.z << 16) | ((unsigned)v.w << 24);
        dtf_s[tid] = (float)dtfs[b * NW + tid];
    }
    __syncthreads();

    float* outb = otf + ((size_t)b * NW + bm0) * NW;

#pragma unroll
    for (int mi = 0; mi < 4; mi++) {
        int r0 = wm0 + mi * 16 + lq, r1 = r0 + 8;
        unsigned qk0 = qk_s[r0], qk1 = qk_s[r1];
        float mq0 = qk0 ? 1.0f : 0.0f, mq1 = qk1 ? 1.0f : 0.0f;
        float rs0 = 0.0f, rs1 = 0.0f;
#pragma unroll
        for (int ni = 0; ni < 8; ni++) {
            int c = wn0 + ni * 8 + q * 2;
            unsigned dk0 = dk_s[c], dk1 = dk_s[c + 1];
            float md0 = dk0 ? 1.0f : 0.0f, md1 = dk1 ? 1.0f : 0.0f;
            float tf0 = dtf_s[c], tf1 = dtf_s[c + 1];
            float v00 = acc[mi][ni][0] * (mq0 * md0);
            float v01 = acc[mi][ni][1] * (mq0 * md1);
            float v10 = acc[mi][ni][2] * (mq1 * md0);
            float v11 = acc[mi][ni][3] * (mq1 * md1);
            *(float2*)(outb + (size_t)r0 * NW + c) = make_float2(v00, v01);
            *(float2*)(outb + (size_t)r1 * NW + c) = make_float2(v10, v11);
            rs0 += (v00 * ABf + (qk0 == dk0 ? EMWf : 0.0f)) * tf0
                 + (v01 * ABf + (qk0 == dk1 ? EMWf : 0.0f)) * tf1;
            rs1 += (v10 * ABf + (qk1 == dk0 ? EMWf : 0.0f)) * tf0
                 + (v11 * ABf + (qk1 == dk1 ? EMWf : 0.0f)) * tf1;
        }
        rs0 += __shfl_xor_sync(0xffffffff, rs0, 1);
        rs0 += __shfl_xor_sync(0xffffffff, rs0, 2);
        rs1 += __shfl_xor_sync(0xffffffff, rs1, 1);
        rs1 += __shfl_xor_sync(0xffffffff, rs1, 2);
        if (q == 0) {
            red_s[(warpId & 3) * BM + r0] = rs0;
            red_s[(warpId & 3) * BM + r1] = rs1;
        }
    }
    __syncthreads();
    if (tid < BM) {
        float e = (red_s[tid] + red_s[BM + tid]) + (red_s[2 * BM + tid] + red_s[3 * BM + tid]);
        g_part[b * NW + bm0 + tid] = e;
    }
}

// ============================================================
// Finisher: BM25 score per batch
// ============================================================
__global__ void final_kernel(const float* __restrict__ qtw, const int* __restrict__ dtfs,
                             float* __restrict__ out) {
    __shared__ float red[256];
    int b = blockIdx.x;
    int t = threadIdx.x;

    float tf = (float)dtfs[b * NW + t];
    red[t] = tf;
    __syncthreads();
#pragma unroll
    for (int s = 128; s > 0; s >>= 1) {
        if (t < s) red[t] += red[t + s];
        __syncthreads();
    }
    float dl = red[0];
    __syncthreads();

    float etdf  = g_part[b * NW + t];
    float denom = etdf * (1.0f + K1f);
    float nom   = etdf + K1f * (1.0f - Bpf + Bpf * dl / AVDLf);
    float v = qtw[b * NW + t] * (denom / (nom + 1e-8f));

    red[t] = v;
    __syncthreads();
#pragma unroll
    for (int s = 128; s > 0; s >>= 1) {
        if (t < s) red[t] += red[t + s];
        __syncthreads();
    }
    if (t == 0) out[b] = red[0];
}

// ============================================================
extern "C" void kernel_launch(void* const* d_in, const int* in_sizes, int n_in,
                              void* d_out, int out_size) {
    const float* q_rep = (const float*)d_in[0];
    const float* d_rep = (const float*)d_in[1];
    const float* qtw   = (const float*)d_in[2];
    const int*   qids  = (const int*)d_in[3];
    const int*   dids  = (const int*)d_in[4];
    const int*   dtfs  = (const int*)d_in[5];

    float* out = (float*)d_out;
    float* otf = out + BATCH;  // d_expanded_tf region

    const int smem = (2 * BM * BK + 2 * BN * BK) * 4;  // 98304 B
    cudaFuncSetAttribute(gemm_kernel, cudaFuncAttributeMaxDynamicSharedMemorySize, smem);

    dim3 grid(NW / BM, BATCH);  // (2, 64)
    gemm_kernel<<<grid, 256, smem>>>(q_rep, d_rep, qids, dids, dtfs, otf);
    final_kernel<<<BATCH, 256>>>(qtw, dtfs, out);
}

// round 9
// speedup vs baseline: 1.7348x; 1.0157x over previous
#include <cuda_runtime.h>
#include <cstdint>

#define BATCH 64
#define NW    256
#define HDIM  768
#define BM    128
#define BN    256
#define BK    32
#define NIT   (HDIM / BK)   // 24
#define STAGES 4

#define K1f    0.1f
#define Bpf    1.2f
#define AVDLf  50.0f
#define ABf    ((float)(0.1 / 768.0))   /* ALPHA*BETA */
#define EMWf   0.9f                     /* 1 - BETA   */

// ---- smem word map ----
#define W_QK    0              // 128 words
#define W_DK    128            // 256
#define W_DTF   384            // 256
#define W_RED   640            // 512 (4 x 128)
#define W_P8    1152           // 8
#define W_R2    1160           // 4
#define W_TILE  1280           // 4 stages x (A 4096 + B 8192)
#define STAGE_W 12288
#define SMEM_BYTES ((W_TILE + STAGES * STAGE_W) * 4)   // 201728

__device__ __forceinline__ void mma_tf32(float& c0, float& c1, float& c2, float& c3,
                                         unsigned a0, unsigned a1, unsigned a2, unsigned a3,
                                         unsigned b0, unsigned b1) {
    asm volatile(
        "mma.sync.aligned.m16n8k8.row.col.f32.tf32.tf32.f32 "
        "{%0,%1,%2,%3}, {%4,%5,%6,%7}, {%8,%9}, {%0,%1,%2,%3};"
        : "+f"(c0), "+f"(c1), "+f"(c2), "+f"(c3)
        : "r"(a0), "r"(a1), "r"(a2), "r"(a3), "r"(b0), "r"(b1));
}

__device__ __forceinline__ void cp16(unsigned dst_smem, const void* src) {
    asm volatile("cp.async.cg.shared.global [%0], [%1], 16;" :: "r"(dst_smem), "l"(src));
}
__device__ __forceinline__ void cp_commit() { asm volatile("cp.async.commit_group;"); }

// round fp32 bits at the tf32 truncation point (HW drops low 13 mantissa bits)
__device__ __forceinline__ unsigned rnd(unsigned x) { return x + 0x1000u; }

// ============================================================
// GEMM + fully fused epilogue (d_expanded_tf + BM25 score).
// grid (2, 64): (M-block, batch). 256 thr, warp grid 2x4, warp tile 64x64.
// 4-stage cp.async ring, prefetch distance 3.
// ============================================================
__global__ __launch_bounds__(256, 1)
void gemm_kernel(const float* __restrict__ qrep, const float* __restrict__ drep,
                 const float* __restrict__ qtw,
                 const int* __restrict__ qids, const int* __restrict__ dids,
                 const int* __restrict__ dtfs, float* __restrict__ otf,
                 float* __restrict__ score) {
    extern __shared__ unsigned sm[];
    const int b   = blockIdx.y;
    const int bm0 = blockIdx.x * BM;
    const int tid = threadIdx.x;
    const int lane = tid & 31;
    const int warpId = tid >> 5;
    const int wm0 = (warpId >> 2) * 64;
    const int wn0 = (warpId & 3) * 64;
    const int q  = lane & 3;
    const int lq = lane >> 2;

    const float* Ag = qrep + ((size_t)b * NW + bm0) * HDIM;
    const float* Bg = drep + (size_t)b * NW * HDIM;

    const unsigned smbase = (unsigned)__cvta_generic_to_shared(sm);

    // ---- epilogue tables (dedicated region, untouched by tile ring) ----
    if (tid < BM) {
        int4 v = ((const int4*)qids)[b * NW + bm0 + tid];
        sm[W_QK + tid] = (unsigned)v.x | ((unsigned)v.y << 8) | ((unsigned)v.z << 16) | ((unsigned)v.w << 24);
    }
    {
        int4 v = ((const int4*)dids)[b * NW + tid];
        sm[W_DK + tid] = (unsigned)v.x | ((unsigned)v.y << 8) | ((unsigned)v.z << 16) | ((unsigned)v.w << 24);
        ((float*)sm)[W_DTF + tid] = (float)dtfs[b * NW + tid];
    }

    float acc[4][8][4];
#pragma unroll
    for (int i = 0; i < 4; i++)
#pragma unroll
        for (int j = 0; j < 8; j++)
#pragma unroll
            for (int k = 0; k < 4; k++) acc[i][j][k] = 0.0f;

    // ---- async tile loaders (16B chunks, XOR-swizzled 128B rows) ----
    auto loadA = [&](int it, int s) {
        const float* src = Ag + it * BK;
        unsigned dstb = smbase + (W_TILE + s * STAGE_W) * 4;
#pragma unroll
        for (int i = 0; i < 4; i++) {
            int c = tid + i * 256;
            int r = c >> 3, g = c & 7;
            unsigned w = r * 32 + ((g ^ (r & 7)) << 2);
            cp16(dstb + w * 4, src + (size_t)r * HDIM + g * 4);
        }
    };
    auto loadB = [&](int it, int s) {
        const float* src = Bg + it * BK;
        unsigned dstb = smbase + (W_TILE + s * STAGE_W + 4096) * 4;
#pragma unroll
        for (int i = 0; i < 8; i++) {
            int c = tid + i * 256;
            int r = c >> 3, g = c & 7;
            unsigned w = r * 32 + ((g ^ (r & 7)) << 2);
            cp16(dstb + w * 4, src + (size_t)r * HDIM + g * 4);
        }
    };

    // prologue: fill stages 0..2
    loadA(0, 0); loadB(0, 0); cp_commit();
    loadA(1, 1); loadB(1, 1); cp_commit();
    loadA(2, 2); loadB(2, 2); cp_commit();

    for (int it = 0; it < NIT; ++it) {
        // ordered retirement: <=2 newer groups pending => group(it) complete
        asm volatile("cp.async.wait_group 2;");
        __syncthreads();   // tile (it) visible to all; all reads of stage (it-1) done

        const int pf = it + 3;
        if (pf < NIT) { loadA(pf, pf & 3); loadB(pf, pf & 3); }
        cp_commit();       // empty groups at tail keep the count uniform

        const unsigned* Ast = sm + W_TILE + (it & 3) * STAGE_W;
        const unsigned* Bst = Ast + 4096;

#pragma unroll
        for (int kk4 = 0; kk4 < 4; kk4++) {       // K-step of 8
            const int g0 = kk4 * 2, g1 = kk4 * 2 + 1;
            unsigned bf0[8], bf1[8];
#pragma unroll
            for (int ni = 0; ni < 8; ni++) {
                int cB = wn0 + ni * 8 + lq;
                bf0[ni] = rnd(Bst[cB * 32 + ((g0 ^ (cB & 7)) << 2) + q]);
                bf1[ni] = rnd(Bst[cB * 32 + ((g1 ^ (cB & 7)) << 2) + q]);
            }
#pragma unroll
            for (int mi = 0; mi < 4; mi++) {
                int r0 = wm0 + mi * 16 + lq, r1 = r0 + 8;
                unsigned a0 = rnd(Ast[r0 * 32 + ((g0 ^ (r0 & 7)) << 2) + q]);
                unsigned a1 = rnd(Ast[r1 * 32 + ((g0 ^ (r1 & 7)) << 2) + q]);
                unsigned a2 = rnd(Ast[r0 * 32 + ((g1 ^ (r0 & 7)) << 2) + q]);
                unsigned a3 = rnd(Ast[r1 * 32 + ((g1 ^ (r1 & 7)) << 2) + q]);
#pragma unroll
                for (int ni = 0; ni < 8; ni++)
                    mma_tf32(acc[mi][ni][0], acc[mi][ni][1], acc[mi][ni][2], acc[mi][ni][3],
                             a0, a1, a2, a3, bf0[ni], bf1[ni]);
            }
        }
    }

    // ---------------- epilogue ----------------
    const unsigned* qk_s  = sm + W_QK;
    const unsigned* dk_s  = sm + W_DK;
    const float*    dtf_s = (const float*)sm + W_DTF;
    float*          red_s = (float*)sm + W_RED;

    // dl partials: each warp reduces its own 32 dtf entries
    {
        float p = dtf_s[warpId * 32 + lane];
#pragma unroll
        for (int o = 16; o > 0; o >>= 1) p += __shfl_xor_sync(0xffffffff, p, o);
        if (lane == 0) ((float*)sm)[W_P8 + warpId] = p;
    }

    float* outb = otf + ((size_t)b * NW + bm0) * NW;

#pragma unroll
    for (int mi = 0; mi < 4; mi++) {
        int r0 = wm0 + mi * 16 + lq, r1 = r0 + 8;
        unsigned qk0 = qk_s[r0], qk1 = qk_s[r1];
        float mq0 = qk0 ? 1.0f : 0.0f, mq1 = qk1 ? 1.0f : 0.0f;
        float rs0 = 0.0f, rs1 = 0.0f;
#pragma unroll
        for (int ni = 0; ni < 8; ni++) {
            int c = wn0 + ni * 8 + q * 2;
            unsigned dk0 = dk_s[c], dk1 = dk_s[c + 1];
            float md0 = dk0 ? 1.0f : 0.0f, md1 = dk1 ? 1.0f : 0.0f;
            float tf0 = dtf_s[c], tf1 = dtf_s[c + 1];
            float v00 = acc[mi][ni][0] * (mq0 * md0);
            float v01 = acc[mi][ni][1] * (mq0 * md1);
            float v10 = acc[mi][ni][2] * (mq1 * md0);
            float v11 = acc[mi][ni][3] * (mq1 * md1);
            *(float2*)(outb + (size_t)r0 * NW + c) = make_float2(v00, v01);
            *(float2*)(outb + (size_t)r1 * NW + c) = make_float2(v10, v11);
            rs0 += (v00 * ABf + (qk0 == dk0 ? EMWf : 0.0f)) * tf0
                 + (v01 * ABf + (qk0 == dk1 ? EMWf : 0.0f)) * tf1;
            rs1 += (v10 * ABf + (qk1 == dk0 ? EMWf : 0.0f)) * tf0
                 + (v11 * ABf + (qk1 == dk1 ? EMWf : 0.0f)) * tf1;
        }
        rs0 += __shfl_xor_sync(0xffffffff, rs0, 1);
        rs0 += __shfl_xor_sync(0xffffffff, rs0, 2);
        rs1 += __shfl_xor_sync(0xffffffff, rs1, 1);
        rs1 += __shfl_xor_sync(0xffffffff, rs1, 2);
        if (q == 0) {
            red_s[(warpId & 3) * BM + r0] = rs0;
            red_s[(warpId & 3) * BM + r1] = rs1;
        }
    }
    __syncthreads();

    // ---- fused BM25 finish: per-CTA partial score, one atomicAdd ----
    float val = 0.0f;
    if (tid < BM) {
        const float* p8 = (const float*)sm + W_P8;
        float dl = ((p8[0] + p8[1]) + (p8[2] + p8[3])) + ((p8[4] + p8[5]) + (p8[6] + p8[7]));
        float etdf = (red_s[tid] + red_s[BM + tid]) + (red_s[2 * BM + tid] + red_s[3 * BM + tid]);
        float denom = etdf * (1.0f + K1f);
        float nom   = etdf + K1f * (1.0f - Bpf + Bpf * dl / AVDLf);
        val = qtw[b * NW + bm0 + tid] * (denom / (nom + 1e-8f));
    }
#pragma unroll
    for (int o = 16; o > 0; o >>= 1) val += __shfl_xor_sync(0xffffffff, val, o);
    if (lane == 0 && warpId < 4) ((float*)sm)[W_R2 + warpId] = val;
    __syncthreads();
    if (tid == 0) {
        const float* r2 = (const float*)sm + W_R2;
        // 2 CTAs per batch: float add of two values is commutative -> deterministic
        atomicAdd(score + b, (r2[0] + r2[1]) + (r2[2] + r2[3]));
    }
}

// ============================================================
extern "C" void kernel_launch(void* const* d_in, const int* in_sizes, int n_in,
                              void* d_out, int out_size) {
    const float* q_rep = (const float*)d_in[0];
    const float* d_rep = (const float*)d_in[1];
    const float* qtw   = (const float*)d_in[2];
    const int*   qids  = (const int*)d_in[3];
    const int*   dids  = (const int*)d_in[4];
    const int*   dtfs  = (const int*)d_in[5];

    float* out = (float*)d_out;
    float* otf = out + BATCH;  // d_expanded_tf region

    cudaMemsetAsync(out, 0, BATCH * sizeof(float));
    cudaFuncSetAttribute(gemm_kernel, cudaFuncAttributeMaxDynamicSharedMemorySize, SMEM_BYTES);

    dim3 grid(NW / BM, BATCH);  // (2, 64)
    gemm_kernel<<<grid, 256, SMEM_BYTES>>>(q_rep, d_rep, qtw, qids, dids, dtfs, otf, out);
}